// round 15
// baseline (speedup 1.0000x reference)
#include <cuda_runtime.h>
#include <cuda_fp16.h>
#include <cstdint>

// GCNFast, block-sparse fp16 GEMM with s-PAIRED CTAs (static grid).
// BM=128 (two s-rows), BN=256 (2 batches). CTA walks the UNION c-list of its
// two rows; X loaded once per stage, A loaded per live row (selective).
// Pairs chosen by GREEDY MAX-INTERSECTION (minimizes union length => fewer
// stages, more both-live stages); pairs LPT-ordered by union length.
//   g_Af[(s,c)] : 8KB fragment-major A block = relu(mask*GCW[t*64+s, t'*64+c])
//   g_Xf[(b,c)] : 16KB fragment-pair-major X block
// 4-stage cp.async ring (48KB/stage), 1 CTA/SM, loads issued 3 stages ahead.
// Mask scan / pairing fused into prep kernel as block 0 (runs first).

namespace {
constexpr int STAGE = 49152;             // 2x8KB A + 2x16KB X
constexpr int SMEM_MAIN = 4 * STAGE;     // 196608
constexpr int SMEM_PREP = 69632;         // prep_fused scratch
}

__device__ uint4 g_Af[(size_t)64 * 64 * 512];    // 32 MB  (block: 512 uint4)
__device__ uint4 g_Xf[(size_t)16 * 64 * 1024];   // 16 MB  (block: 1024 uint4)
__device__ int g_plen[32];
__device__ unsigned char g_plist[32][64];
__device__ unsigned char g_pflag[32][64];        // bit0: sLo live, bit1: sHi live
__device__ unsigned char g_pairs[32][2];

__device__ __forceinline__ void mma16(float (&c)[4], const uint4& a, unsigned b0, unsigned b1) {
    asm volatile(
        "mma.sync.aligned.m16n8k16.row.col.f32.f16.f16.f32 "
        "{%0,%1,%2,%3}, {%4,%5,%6,%7}, {%8,%9}, {%0,%1,%2,%3};"
        : "+f"(c[0]), "+f"(c[1]), "+f"(c[2]), "+f"(c[3])
        : "r"(a.x), "r"(a.y), "r"(a.z), "r"(a.w), "r"(b0), "r"(b1));
}
__device__ __forceinline__ void cp16(void* dst, const void* src) {
    unsigned s = (unsigned)__cvta_generic_to_shared(dst);
    asm volatile("cp.async.cg.shared.global [%0], [%1], 16;" :: "r"(s), "l"(src));
}
__device__ __forceinline__ unsigned packh2(float lo, float hi) {
    __half2 h = __floats2half2_rn(lo, hi);
    return *(unsigned*)&h;
}

// ---- fused prep: 0 = mask+pairing, [1,257) g_Af, [257,1281) g_Xf ----
__global__ void __launch_bounds__(256)
prep_fused_kernel(const float* __restrict__ AAm,
                  const float4* __restrict__ GCW4,
                  const float4* __restrict__ h4) {
    extern __shared__ float sm[];
    const int tid = threadIdx.x;
    const int bid = blockIdx.x;

    if (bid == 0) {
        // ---- mask scan (warp ballot) + greedy max-intersection pairing ----
        __shared__ unsigned long long rmask[64];
        __shared__ int cnts[64];
        __shared__ unsigned char order_sm[64];
        __shared__ int paired[64];
        __shared__ int score[64];
        __shared__ int curs;
        __shared__ unsigned char pA[32], pB[32];
        __shared__ int ulen[32];
        const int w = tid >> 5, lane = tid & 31;
        #pragma unroll
        for (int r = 0; r < 8; ++r) {
            int s = w * 8 + r;
            float v0 = AAm[(size_t)s * 4096 + lane];
            float v1 = AAm[(size_t)s * 4096 + lane + 32];
            unsigned lo = __ballot_sync(0xffffffffu, v0 != 0.0f);
            unsigned hi = __ballot_sync(0xffffffffu, v1 != 0.0f);
            if (lane == 0) rmask[s] = (unsigned long long)lo |
                                      ((unsigned long long)hi << 32);
        }
        __syncthreads();
        if (tid < 64) {
            cnts[tid] = __popcll(rmask[tid]);
            paired[tid] = 0;
        }
        __syncthreads();
        if (tid < 64) {        // rank by count desc (processing order)
            int c = cnts[tid], rank = 0;
            #pragma unroll 8
            for (int j = 0; j < 64; ++j) {
                int cj = cnts[j];
                if (cj > c || (cj == c && j < tid)) ++rank;
            }
            order_sm[rank] = (unsigned char)tid;
        }
        __syncthreads();
        for (int r = 0; r < 32; ++r) {
            if (tid == 0) {    // next unpaired row (densest first)
                int k = 0;
                while (paired[order_sm[k]]) ++k;
                int c0 = order_sm[k];
                paired[c0] = 1;
                curs = c0;
            }
            __syncthreads();
            const int cur = curs;
            if (tid < 64)
                score[tid] = paired[tid] ? -1 :
                    (int)__popcll(rmask[cur] & rmask[tid]) * 256 + cnts[tid];
            __syncthreads();
            if (tid < 32) {    // warp argmax over 64 scores
                int s0 = score[tid], i0 = tid;
                int s1 = score[tid + 32];
                if (s1 > s0) { s0 = s1; i0 = tid + 32; }
                #pragma unroll
                for (int off = 16; off; off >>= 1) {
                    int so = __shfl_down_sync(0xffffffffu, s0, off);
                    int io = __shfl_down_sync(0xffffffffu, i0, off);
                    if (so > s0) { s0 = so; i0 = io; }
                }
                if (tid == 0) {
                    paired[i0] = 1;
                    pA[r] = (unsigned char)cur;
                    pB[r] = (unsigned char)i0;
                    ulen[r] = (int)__popcll(rmask[cur] | rmask[i0]);
                }
            }
            __syncthreads();
        }
        // LPT order pairs by union length desc; build union lists
        if (tid < 32) {
            int u = ulen[tid], rank = 0;
            #pragma unroll 8
            for (int j = 0; j < 32; ++j) {
                int uj = ulen[j];
                if (uj > u || (uj == u && j < tid)) ++rank;
            }
            int sLo = pA[tid], sHi = pB[tid];
            unsigned long long mLo = rmask[sLo], mHi = rmask[sHi];
            int len = 0;
            for (int c = 0; c < 64; ++c) {
                int f = (int)((mLo >> c) & 1ull) | ((int)((mHi >> c) & 1ull) << 1);
                if (f) {
                    g_plist[rank][len] = (unsigned char)c;
                    g_pflag[rank][len] = (unsigned char)f;
                    ++len;
                }
            }
            g_plen[rank] = len;
            g_pairs[rank][0] = (unsigned char)sLo;
            g_pairs[rank][1] = (unsigned char)sHi;
        }
    } else if (bid < 257) {
        // ---- A branch: (c16 = ab&3, s = ab>>2) ----
        __shared__ float maskv[16];
        const int ab = bid - 1;
        const int c16 = ab & 3, s = ab >> 2;
        if (tid < 16) maskv[tid] = AAm[(size_t)s * 4096 + c16 * 16 + tid];
        __syncthreads();
        for (int kk = 0; kk < 4; ++kk) {
            #pragma unroll
            for (int p = 0; p < 16; ++p) {
                int idx = tid + p * 256;
                int t = idx >> 6, tl = (idx >> 2) & 15, f = idx & 3;
                float4 v = GCW4[(size_t)(t * 64 + s) * 1024 + (kk * 16 + tl) * 16 + c16 * 4 + f];
                float* dst = sm + t * 272 + tl * 17 + f * 4;
                dst[0] = maskv[f * 4 + 0] != 0.f ? fmaxf(v.x, 0.f) : 0.f;
                dst[1] = maskv[f * 4 + 1] != 0.f ? fmaxf(v.y, 0.f) : 0.f;
                dst[2] = maskv[f * 4 + 2] != 0.f ? fmaxf(v.z, 0.f) : 0.f;
                dst[3] = maskv[f * 4 + 3] != 0.f ? fmaxf(v.w, 0.f) : 0.f;
            }
            __syncthreads();
            #pragma unroll
            for (int p = 0; p < 8; ++p) {
                int idx = tid + p * 256;
                int lane = idx & 31, mslab = (idx >> 5) & 3, c = idx >> 7;
                if (maskv[c] != 0.f) {       // store only live (s,c) blocks
                    int g = lane >> 2, q = lane & 3;
                    int r0 = mslab * 16 + g;
                    const float* b0 = sm + r0 * 272 + c;
                    const float* b8 = b0 + 8 * 272;
                    uint4 o;
                    o.x = packh2(b0[2 * q * 17],       b0[(2 * q + 1) * 17]);
                    o.y = packh2(b8[2 * q * 17],       b8[(2 * q + 1) * 17]);
                    o.z = packh2(b0[(2 * q + 8) * 17], b0[(2 * q + 9) * 17]);
                    o.w = packh2(b8[(2 * q + 8) * 17], b8[(2 * q + 9) * 17]);
                    g_Af[(((size_t)s * 64 + c16 * 16 + c) << 9) + kk * 128 + mslab * 32 + lane] = o;
                }
            }
            __syncthreads();
        }
    } else {
        // ---- X branch: (c, b) ----
        const int idx0 = bid - 257;
        const int c = idx0 & 63, b = idx0 >> 6;
        #pragma unroll
        for (int p = 0; p < 8; ++p) {
            int idx = tid + p * 256;
            int tp = idx >> 5, d4 = idx & 31;
            float4 v = h4[(size_t)((b * 64 + c) * 64 + tp) * 32 + d4];
            float* dst = sm + tp * 132 + d4 * 4;
            dst[0] = v.x; dst[1] = v.y; dst[2] = v.z; dst[3] = v.w;
        }
        __syncthreads();
        #pragma unroll
        for (int p = 0; p < 4; ++p) {
            int idx = tid + p * 256;
            int lane = idx & 31, np = (idx >> 5) & 7, kk = idx >> 8;
            int g = lane >> 2, q = lane & 3;
            int d0 = np * 16 + g;
            const float* base = sm + (kk * 16 + 2 * q) * 132;
            uint4 o;
            o.x = packh2(base[d0],           base[132 + d0]);
            o.y = packh2(base[8 * 132 + d0], base[9 * 132 + d0]);
            o.z = packh2(base[d0 + 8],           base[132 + d0 + 8]);
            o.w = packh2(base[8 * 132 + d0 + 8], base[9 * 132 + d0 + 8]);
            g_Xf[(((size_t)b * 64 + c) << 10) + kk * 256 + np * 32 + lane] = o;
        }
    }
}

// ---- main: s-paired block-sparse GEMM, BM=128, BN=256, 4-stage ring ----
__global__ void __launch_bounds__(256, 1)
gcn_sp_kernel(const float* __restrict__ GCB, float* __restrict__ out)
{
    extern __shared__ char smem[];
    __shared__ unsigned char sc[64], sf[64];
    const int tid = threadIdx.x;
    const int bx = blockIdx.x;                 // batch pair: 2bx, 2bx+1
    const int pr = blockIdx.y;                 // s-pair (longest first)

    const int sLo = g_pairs[pr][0], sHi = g_pairs[pr][1];
    const int n = g_plen[pr];
    if (tid < 64) {
        sc[tid] = g_plist[pr][tid];
        sf[tid] = g_pflag[pr][tid];
    }
    __syncthreads();

    const uint4* gX0 = g_Xf + (((size_t)(bx * 2 + 0) * 64) << 10);
    const uint4* gX1 = g_Xf + (((size_t)(bx * 2 + 1) * 64) << 10);

    auto load_stage = [&](int ki) {
        const int c = sc[ki];
        const int f = sf[ki];
        char* st = smem + (ki & 3) * STAGE;
        if (f & 1) {
            const uint4* gA = g_Af + (((size_t)sLo * 64 + c) << 9);
            cp16(st + tid * 16, gA + tid);
            cp16(st + (tid + 256) * 16, gA + tid + 256);
        }
        if (f & 2) {
            const uint4* gA = g_Af + (((size_t)sHi * 64 + c) << 9);
            cp16(st + 8192 + tid * 16, gA + tid);
            cp16(st + 8192 + (tid + 256) * 16, gA + tid + 256);
        }
        #pragma unroll
        for (int p = 0; p < 4; ++p) {
            int ch = tid + p * 256;
            cp16(st + 16384 + ch * 16, gX0 + ((size_t)c << 10) + ch);
        }
        #pragma unroll
        for (int p = 0; p < 4; ++p) {
            int ch = tid + p * 256;
            cp16(st + 32768 + ch * 16, gX1 + ((size_t)c << 10) + ch);
        }
        asm volatile("cp.async.commit_group;" ::: "memory");
    };

    const int lane = tid & 31, wid = tid >> 5;
    const int mhalf = wid >> 2;   // 0 -> sLo, 1 -> sHi
    const int wn = wid & 3;       // 64-wide N group; wn>>1 = batch half
    const int g = lane >> 2, q = lane & 3;

    float acc[4][8][4];
    #pragma unroll
    for (int a = 0; a < 4; ++a)
        #pragma unroll
        for (int bb = 0; bb < 8; ++bb)
            #pragma unroll
            for (int v = 0; v < 4; ++v) acc[a][bb][v] = 0.f;

    if (n > 0) load_stage(0);
    if (n > 1) load_stage(1);
    if (n > 2) load_stage(2);

    for (int ki = 0; ki < n; ++ki) {
        const int rem = n - 1 - ki;
        if (rem >= 2)      asm volatile("cp.async.wait_group 2;" ::: "memory");
        else if (rem == 1) asm volatile("cp.async.wait_group 1;" ::: "memory");
        else               asm volatile("cp.async.wait_group 0;" ::: "memory");
        __syncthreads();
        if (ki + 3 < n) load_stage(ki + 3);

        const char* st = smem + (ki & 3) * STAGE;
        const int f = sf[ki];
        if ((f >> mhalf) & 1) {
            const char* sa = st + mhalf * 8192;
            const char* sx = st + 16384 + (wn >> 1) * 16384;
            #pragma unroll
            for (int kk = 0; kk < 4; ++kk) {
                uint4 xq[4];
                #pragma unroll
                for (int j = 0; j < 4; ++j) {
                    int np = (wn & 1) * 4 + j;
                    xq[j] = *(const uint4*)(sx + ((kk * 256 + np * 32 + lane) << 4));
                }
                #pragma unroll
                for (int mt = 0; mt < 4; ++mt) {
                    uint4 af = *(const uint4*)(sa + ((kk * 128 + mt * 32 + lane) << 4));
                    #pragma unroll
                    for (int j = 0; j < 4; ++j) {
                        mma16(acc[mt][2 * j + 0], af, xq[j].x, xq[j].y);
                        mma16(acc[mt][2 * j + 1], af, xq[j].z, xq[j].w);
                    }
                }
            }
        }
    }

    // Epilogue: s from mhalf; t = M row; d/b from (wn, frag).
    const int s = mhalf ? sHi : sLo;
    const int b = bx * 2 + (wn >> 1);
    #pragma unroll
    for (int mt = 0; mt < 4; ++mt) {
        #pragma unroll
        for (int r = 0; r < 2; ++r) {
            const int t = mt * 16 + g + r * 8;
            const float* brow = GCB + ((size_t)(t * 64 + s) << 7);
            float* orow = out + (((size_t)(b * 64 + s) * 64 + t) << 7);
            #pragma unroll
            for (int j = 0; j < 4; ++j) {
                #pragma unroll
                for (int hb = 0; hb < 2; ++hb) {
                    const int d0 = (wn & 1) * 64 + j * 16 + hb * 8 + q * 2;
                    float2 bias = *(const float2*)(brow + d0);
                    float2 v;
                    v.x = fmaxf(acc[mt][2 * j + hb][r * 2 + 0] + bias.x, 0.f);
                    v.y = fmaxf(acc[mt][2 * j + hb][r * 2 + 1] + bias.y, 0.f);
                    *(float2*)(orow + d0) = v;
                }
            }
        }
    }
}

extern "C" void kernel_launch(void* const* d_in, const int* in_sizes, int n_in,
                              void* d_out, int out_size) {
    // metadata order: h, e, AA_mask, GCW, GCB
    const float* h   = (const float*)d_in[0];
    const float* AAm = (const float*)d_in[2];
    const float* GCW = (const float*)d_in[3];
    const float* GCB = (const float*)d_in[4];
    float* out = (float*)d_out;

    cudaFuncSetAttribute(prep_fused_kernel,
                         cudaFuncAttributeMaxDynamicSharedMemorySize, SMEM_PREP);
    prep_fused_kernel<<<1281, 256, SMEM_PREP>>>(AAm, (const float4*)GCW,
                                                (const float4*)h);

    cudaFuncSetAttribute(gcn_sp_kernel,
                         cudaFuncAttributeMaxDynamicSharedMemorySize, SMEM_MAIN);
    dim3 grid(8, 32);   // (batch pair, s-pair)
    gcn_sp_kernel<<<grid, 256, SMEM_MAIN>>>(GCB, out);
}

// round 16
// speedup vs baseline: 1.1727x; 1.1727x over previous
#include <cuda_runtime.h>
#include <cuda_fp16.h>
#include <cstdint>

// GCNFast, block-sparse fp16 GEMM with s-PAIRED CTAs (static grid).
// BM=128 (two s-rows), BN=256 (2 batches). CTA walks the UNION c-list of its
// two rows; X loaded once per stage, A loaded per live row (selective).
// Pairs = rank-adjacent by row density (cheap parallel rank), LPT-ordered.
//   g_Af[(s,c)] : 8KB fragment-major A block = relu(mask*GCW[t*64+s, t'*64+c])
//   g_Xf[(b,c)] : 16KB fragment-pair-major X block
// 4-stage cp.async ring (48KB/stage), 1 CTA/SM, loads issued 3 stages ahead.
// Prep: 2049 light blocks — bid 0 mask/pairing, [1,1025) A per-kk, [1025,2049) X.

namespace {
constexpr int STAGE = 49152;             // 2x8KB A + 2x16KB X
constexpr int SMEM_MAIN = 4 * STAGE;     // 196608
constexpr int SMEM_PREP = 69632;         // A-branch scratch (64*272 floats)
}

__device__ uint4 g_Af[(size_t)64 * 64 * 512];    // 32 MB  (block: 512 uint4)
__device__ uint4 g_Xf[(size_t)16 * 64 * 1024];   // 16 MB  (block: 1024 uint4)
__device__ int g_plen[32];
__device__ unsigned char g_plist[32][64];
__device__ unsigned char g_pflag[32][64];        // bit0: sLo live, bit1: sHi live
__device__ unsigned char g_pairs[32][2];

__device__ __forceinline__ void mma16(float (&c)[4], const uint4& a, unsigned b0, unsigned b1) {
    asm volatile(
        "mma.sync.aligned.m16n8k16.row.col.f32.f16.f16.f32 "
        "{%0,%1,%2,%3}, {%4,%5,%6,%7}, {%8,%9}, {%0,%1,%2,%3};"
        : "+f"(c[0]), "+f"(c[1]), "+f"(c[2]), "+f"(c[3])
        : "r"(a.x), "r"(a.y), "r"(a.z), "r"(a.w), "r"(b0), "r"(b1));
}
__device__ __forceinline__ void cp16(void* dst, const void* src) {
    unsigned s = (unsigned)__cvta_generic_to_shared(dst);
    asm volatile("cp.async.cg.shared.global [%0], [%1], 16;" :: "r"(s), "l"(src));
}
__device__ __forceinline__ unsigned packh2(float lo, float hi) {
    __half2 h = __floats2half2_rn(lo, hi);
    return *(unsigned*)&h;
}

// ---- fused prep: bid 0 mask/pairing; [1,1025) A per-kk; [1025,2049) X ----
__global__ void __launch_bounds__(256)
prep_fused_kernel(const float* __restrict__ AAm,
                  const float4* __restrict__ GCW4,
                  const float4* __restrict__ h4) {
    extern __shared__ float sm[];
    const int tid = threadIdx.x;
    const int bid = blockIdx.x;

    if (bid == 0) {
        // ---- mask scan (warp ballot) + rank pairing + union lists ----
        __shared__ unsigned long long rmask[64];
        __shared__ int cnts[64];
        __shared__ unsigned char order_sm[64];
        const int w = tid >> 5, lane = tid & 31;
        #pragma unroll
        for (int r = 0; r < 8; ++r) {
            int s = w * 8 + r;
            float v0 = AAm[(size_t)s * 4096 + lane];
            float v1 = AAm[(size_t)s * 4096 + lane + 32];
            unsigned lo = __ballot_sync(0xffffffffu, v0 != 0.0f);
            unsigned hi = __ballot_sync(0xffffffffu, v1 != 0.0f);
            if (lane == 0) rmask[s] = (unsigned long long)lo |
                                      ((unsigned long long)hi << 32);
        }
        __syncthreads();
        if (tid < 64) cnts[tid] = __popcll(rmask[tid]);
        __syncthreads();
        if (tid < 64) {
            int c = cnts[tid], rank = 0;
            #pragma unroll 8
            for (int j = 0; j < 64; ++j) {
                int cj = cnts[j];
                if (cj > c || (cj == c && j < tid)) ++rank;
            }
            order_sm[rank] = (unsigned char)tid;
        }
        __syncthreads();
        if (tid < 32) {
            int p = tid;
            int sLo = order_sm[2 * p], sHi = order_sm[2 * p + 1];
            unsigned long long mLo = rmask[sLo], mHi = rmask[sHi];
            int len = 0;
            for (int c = 0; c < 64; ++c) {
                int f = (int)((mLo >> c) & 1ull) | ((int)((mHi >> c) & 1ull) << 1);
                if (f) {
                    g_plist[p][len] = (unsigned char)c;
                    g_pflag[p][len] = (unsigned char)f;
                    ++len;
                }
            }
            g_plen[p] = len;
            g_pairs[p][0] = (unsigned char)sLo;
            g_pairs[p][1] = (unsigned char)sHi;
        }
    } else if (bid < 1025) {
        // ---- A branch, one kk pass: ab = bid-1 -> (kk, c16, s) ----
        __shared__ float maskv[16];
        const int ab = bid - 1;
        const int kk = ab & 3, c16 = (ab >> 2) & 3, s = ab >> 4;
        if (tid < 16) maskv[tid] = AAm[(size_t)s * 4096 + c16 * 16 + tid];
        __syncthreads();
        #pragma unroll
        for (int p = 0; p < 16; ++p) {
            int idx = tid + p * 256;                   // 4096 float4 reads
            int t = idx >> 6, tl = (idx >> 2) & 15, f = idx & 3;
            float4 v = GCW4[(size_t)(t * 64 + s) * 1024 + (kk * 16 + tl) * 16 + c16 * 4 + f];
            float* dst = sm + t * 272 + tl * 17 + f * 4;
            dst[0] = maskv[f * 4 + 0] != 0.f ? fmaxf(v.x, 0.f) : 0.f;
            dst[1] = maskv[f * 4 + 1] != 0.f ? fmaxf(v.y, 0.f) : 0.f;
            dst[2] = maskv[f * 4 + 2] != 0.f ? fmaxf(v.z, 0.f) : 0.f;
            dst[3] = maskv[f * 4 + 3] != 0.f ? fmaxf(v.w, 0.f) : 0.f;
        }
        __syncthreads();
        #pragma unroll
        for (int p = 0; p < 8; ++p) {
            int idx = tid + p * 256;                   // 2048 fragment slots
            int lane = idx & 31, mslab = (idx >> 5) & 3, c = idx >> 7;
            if (maskv[c] != 0.f) {       // store only live (s,c) blocks
                int g = lane >> 2, q = lane & 3;
                int r0 = mslab * 16 + g;
                const float* b0 = sm + r0 * 272 + c;
                const float* b8 = b0 + 8 * 272;
                uint4 o;
                o.x = packh2(b0[2 * q * 17],       b0[(2 * q + 1) * 17]);
                o.y = packh2(b8[2 * q * 17],       b8[(2 * q + 1) * 17]);
                o.z = packh2(b0[(2 * q + 8) * 17], b0[(2 * q + 9) * 17]);
                o.w = packh2(b8[(2 * q + 8) * 17], b8[(2 * q + 9) * 17]);
                g_Af[(((size_t)s * 64 + c16 * 16 + c) << 9) + kk * 128 + mslab * 32 + lane] = o;
            }
        }
    } else {
        // ---- X branch: (c, b) ----
        const int idx0 = bid - 1025;
        const int c = idx0 & 63, b = idx0 >> 6;
        #pragma unroll
        for (int p = 0; p < 8; ++p) {
            int idx = tid + p * 256;                   // 2048 float4
            int tp = idx >> 5, d4 = idx & 31;
            float4 v = h4[(size_t)((b * 64 + c) * 64 + tp) * 32 + d4];
            float* dst = sm + tp * 132 + d4 * 4;
            dst[0] = v.x; dst[1] = v.y; dst[2] = v.z; dst[3] = v.w;
        }
        __syncthreads();
        #pragma unroll
        for (int p = 0; p < 4; ++p) {
            int idx = tid + p * 256;                   // 1024 uint4 slots
            int lane = idx & 31, np = (idx >> 5) & 7, kk = idx >> 8;
            int g = lane >> 2, q = lane & 3;
            int d0 = np * 16 + g;
            const float* base = sm + (kk * 16 + 2 * q) * 132;
            uint4 o;
            o.x = packh2(base[d0],           base[132 + d0]);
            o.y = packh2(base[8 * 132 + d0], base[9 * 132 + d0]);
            o.z = packh2(base[d0 + 8],           base[132 + d0 + 8]);
            o.w = packh2(base[8 * 132 + d0 + 8], base[9 * 132 + d0 + 8]);
            g_Xf[(((size_t)b * 64 + c) << 10) + kk * 256 + np * 32 + lane] = o;
        }
    }
}

// ---- main: s-paired block-sparse GEMM, BM=128, BN=256, 4-stage ring ----
__global__ void __launch_bounds__(256, 1)
gcn_sp_kernel(const float* __restrict__ GCB, float* __restrict__ out)
{
    extern __shared__ char smem[];
    __shared__ unsigned char sc[64], sf[64];
    const int tid = threadIdx.x;
    const int bx = blockIdx.x;                 // batch pair: 2bx, 2bx+1
    const int pr = blockIdx.y;                 // s-pair (longest first)

    const int sLo = g_pairs[pr][0], sHi = g_pairs[pr][1];
    const int n = g_plen[pr];
    if (tid < 64) {
        sc[tid] = g_plist[pr][tid];
        sf[tid] = g_pflag[pr][tid];
    }
    __syncthreads();

    const uint4* gX0 = g_Xf + (((size_t)(bx * 2 + 0) * 64) << 10);
    const uint4* gX1 = g_Xf + (((size_t)(bx * 2 + 1) * 64) << 10);

    auto load_stage = [&](int ki) {
        const int c = sc[ki];
        const int f = sf[ki];
        char* st = smem + (ki & 3) * STAGE;
        if (f & 1) {
            const uint4* gA = g_Af + (((size_t)sLo * 64 + c) << 9);
            cp16(st + tid * 16, gA + tid);
            cp16(st + (tid + 256) * 16, gA + tid + 256);
        }
        if (f & 2) {
            const uint4* gA = g_Af + (((size_t)sHi * 64 + c) << 9);
            cp16(st + 8192 + tid * 16, gA + tid);
            cp16(st + 8192 + (tid + 256) * 16, gA + tid + 256);
        }
        #pragma unroll
        for (int p = 0; p < 4; ++p) {
            int ch = tid + p * 256;
            cp16(st + 16384 + ch * 16, gX0 + ((size_t)c << 10) + ch);
        }
        #pragma unroll
        for (int p = 0; p < 4; ++p) {
            int ch = tid + p * 256;
            cp16(st + 32768 + ch * 16, gX1 + ((size_t)c << 10) + ch);
        }
        asm volatile("cp.async.commit_group;" ::: "memory");
    };

    const int lane = tid & 31, wid = tid >> 5;
    const int mhalf = wid >> 2;   // 0 -> sLo, 1 -> sHi
    const int wn = wid & 3;       // 64-wide N group; wn>>1 = batch half
    const int g = lane >> 2, q = lane & 3;

    float acc[4][8][4];
    #pragma unroll
    for (int a = 0; a < 4; ++a)
        #pragma unroll
        for (int bb = 0; bb < 8; ++bb)
            #pragma unroll
            for (int v = 0; v < 4; ++v) acc[a][bb][v] = 0.f;

    if (n > 0) load_stage(0);
    if (n > 1) load_stage(1);
    if (n > 2) load_stage(2);

    for (int ki = 0; ki < n; ++ki) {
        const int rem = n - 1 - ki;
        if (rem >= 2)      asm volatile("cp.async.wait_group 2;" ::: "memory");
        else if (rem == 1) asm volatile("cp.async.wait_group 1;" ::: "memory");
        else               asm volatile("cp.async.wait_group 0;" ::: "memory");
        __syncthreads();
        if (ki + 3 < n) load_stage(ki + 3);

        const char* st = smem + (ki & 3) * STAGE;
        const int f = sf[ki];
        if ((f >> mhalf) & 1) {
            const char* sa = st + mhalf * 8192;
            const char* sx = st + 16384 + (wn >> 1) * 16384;
            #pragma unroll
            for (int kk = 0; kk < 4; ++kk) {
                uint4 xq[4];
                #pragma unroll
                for (int j = 0; j < 4; ++j) {
                    int np = (wn & 1) * 4 + j;
                    xq[j] = *(const uint4*)(sx + ((kk * 256 + np * 32 + lane) << 4));
                }
                #pragma unroll
                for (int mt = 0; mt < 4; ++mt) {
                    uint4 af = *(const uint4*)(sa + ((kk * 128 + mt * 32 + lane) << 4));
                    #pragma unroll
                    for (int j = 0; j < 4; ++j) {
                        mma16(acc[mt][2 * j + 0], af, xq[j].x, xq[j].y);
                        mma16(acc[mt][2 * j + 1], af, xq[j].z, xq[j].w);
                    }
                }
            }
        }
    }

    // Epilogue: s from mhalf; t = M row; d/b from (wn, frag).
    const int s = mhalf ? sHi : sLo;
    const int b = bx * 2 + (wn >> 1);
    #pragma unroll
    for (int mt = 0; mt < 4; ++mt) {
        #pragma unroll
        for (int r = 0; r < 2; ++r) {
            const int t = mt * 16 + g + r * 8;
            const float* brow = GCB + ((size_t)(t * 64 + s) << 7);
            float* orow = out + (((size_t)(b * 64 + s) * 64 + t) << 7);
            #pragma unroll
            for (int j = 0; j < 4; ++j) {
                #pragma unroll
                for (int hb = 0; hb < 2; ++hb) {
                    const int d0 = (wn & 1) * 64 + j * 16 + hb * 8 + q * 2;
                    float2 bias = *(const float2*)(brow + d0);
                    float2 v;
                    v.x = fmaxf(acc[mt][2 * j + hb][r * 2 + 0] + bias.x, 0.f);
                    v.y = fmaxf(acc[mt][2 * j + hb][r * 2 + 1] + bias.y, 0.f);
                    *(float2*)(orow + d0) = v;
                }
            }
        }
    }
}

extern "C" void kernel_launch(void* const* d_in, const int* in_sizes, int n_in,
                              void* d_out, int out_size) {
    // metadata order: h, e, AA_mask, GCW, GCB
    const float* h   = (const float*)d_in[0];
    const float* AAm = (const float*)d_in[2];
    const float* GCW = (const float*)d_in[3];
    const float* GCB = (const float*)d_in[4];
    float* out = (float*)d_out;

    cudaFuncSetAttribute(prep_fused_kernel,
                         cudaFuncAttributeMaxDynamicSharedMemorySize, SMEM_PREP);
    prep_fused_kernel<<<2049, 256, SMEM_PREP>>>(AAm, (const float4*)GCW,
                                                (const float4*)h);

    cudaFuncSetAttribute(gcn_sp_kernel,
                         cudaFuncAttributeMaxDynamicSharedMemorySize, SMEM_MAIN);
    dim3 grid(8, 32);   // (batch pair, s-pair)
    gcn_sp_kernel<<<grid, 256, SMEM_MAIN>>>(GCB, out);
}